// round 3
// baseline (speedup 1.0000x reference)
#include <cuda_runtime.h>

#define NB 8
#define SEQ 1024
#define SFULL 1025
#define EMB 768
#define NH 12
#define HD 64
#define BH (NB*NH)   // 96

typedef unsigned long long ull;

// ---- packed f32x2 helpers (FFMA2 is PTX-only; ptxas never emits it from C++) ----
__device__ __forceinline__ ull pk2(float lo, float hi) {
    ull r; asm("mov.b64 %0,{%1,%2};" : "=l"(r) : "f"(lo), "f"(hi)); return r;
}
__device__ __forceinline__ void fma2(ull& d, ull a, ull b) {
    asm("fma.rn.f32x2 %0,%1,%2,%0;" : "+l"(d) : "l"(a), "l"(b));
}
__device__ __forceinline__ float2 upk(ull v) {
    float2 r; asm("mov.b64 {%0,%1},%2;" : "=f"(r.x), "=f"(r.y) : "l"(v)); return r;
}

// Scratch (module-static device globals are allowed; runtime allocs are not)
__device__ float g_Q[NB*SEQ*EMB];
__device__ float g_K[NB*SEQ*EMB];
__device__ float g_V[NB*SEQ*EMB];
__device__ float g_Y[NB*SFULL*EMB];
__device__ float g_C[NB*EMB];
__device__ float g_coef[BH*SEQ];
__device__ float g_ck[BH*SEQ];

// ---------------------------------------------------------------------------
// Fused Q/K/V projection:  C[M=8192, N=768] = xt[M,768] @ W^T + b
// 128x128x8 tile, 256 threads, 8x8 micro-tile, f32x2 packed math.
// Accumulators paired over rows: acc2[ip][j], ip=0..3 row-pairs, j=0..7 cols.
// ---------------------------------------------------------------------------
__global__ __launch_bounds__(256) void qkv_gemm(
    const float* __restrict__ x,
    const float* __restrict__ Wq, const float* __restrict__ bq,
    const float* __restrict__ Wk, const float* __restrict__ bk,
    const float* __restrict__ Wv, const float* __restrict__ bv)
{
    const float* W; const float* bias; float* C;
    int z = blockIdx.z;
    if (z == 0)      { W = Wq; bias = bq; C = g_Q; }
    else if (z == 1) { W = Wk; bias = bk; C = g_K; }
    else             { W = Wv; bias = bv; C = g_V; }

    __shared__ float As[8][128];
    __shared__ float Bs[8][128];

    int tid = threadIdx.x;
    int ty = tid >> 4, tx = tid & 15;
    int lr = tid >> 1;
    int lc = (tid & 1) << 2;
    int bm = blockIdx.y << 7;
    int bn = blockIdx.x << 7;

    int ar = bm + lr;
    const float* Arow = x + (size_t)((ar >> 10) * SFULL + 1 + (ar & 1023)) * EMB;
    const float* Brow = W + (size_t)(bn + lr) * EMB;

    ull acc2[4][8];
#pragma unroll
    for (int i = 0; i < 4; i++)
#pragma unroll
        for (int j = 0; j < 8; j++) acc2[i][j] = 0ull;

    for (int k0 = 0; k0 < EMB; k0 += 8) {
        float4 a4 = *(const float4*)(Arow + k0 + lc);
        float4 b4 = *(const float4*)(Brow + k0 + lc);
        __syncthreads();
        As[lc+0][lr] = a4.x; As[lc+1][lr] = a4.y; As[lc+2][lr] = a4.z; As[lc+3][lr] = a4.w;
        Bs[lc+0][lr] = b4.x; Bs[lc+1][lr] = b4.y; Bs[lc+2][lr] = b4.z; Bs[lc+3][lr] = b4.w;
        __syncthreads();
#pragma unroll
        for (int k = 0; k < 8; k++) {
            ulonglong2 a01 = *(const ulonglong2*)&As[k][ty*4];        // row pairs 0,1
            ulonglong2 a23 = *(const ulonglong2*)&As[k][64 + ty*4];   // row pairs 2,3
            float4 b0 = *(const float4*)&Bs[k][tx*4];
            float4 b1 = *(const float4*)&Bs[k][64 + tx*4];
            ull a2[4] = {a01.x, a01.y, a23.x, a23.y};
            ull bb[8] = {pk2(b0.x,b0.x), pk2(b0.y,b0.y), pk2(b0.z,b0.z), pk2(b0.w,b0.w),
                         pk2(b1.x,b1.x), pk2(b1.y,b1.y), pk2(b1.z,b1.z), pk2(b1.w,b1.w)};
#pragma unroll
            for (int i = 0; i < 4; i++)
#pragma unroll
                for (int j = 0; j < 8; j++)
                    fma2(acc2[i][j], a2[i], bb[j]);
        }
    }

#pragma unroll
    for (int p = 0; p < 4; p++) {
        int rbase = (p < 2) ? (bm + ty*4 + 2*p) : (bm + 64 + ty*4 + 2*(p-2));
        float* crow0 = C + (size_t)rbase * EMB;
        float* crow1 = C + (size_t)(rbase+1) * EMB;
#pragma unroll
        for (int j = 0; j < 8; j++) {
            int col = bn + ((j < 4) ? tx*4 + j : 64 + tx*4 + (j-4));
            float2 v = upk(acc2[p][j]);
            float bv_ = bias[col];
            crow0[col] = v.x + bv_;
            crow1[col] = v.y + bv_;
        }
    }
}

// ---------------------------------------------------------------------------
// Output projection: out[M=8200,768] = g_Y @ Wo^T + bo (f32x2)
// ---------------------------------------------------------------------------
__global__ __launch_bounds__(256) void out_gemm(
    const float* __restrict__ Wo, const float* __restrict__ bo,
    float* __restrict__ out)
{
    const int M = NB * SFULL; // 8200
    __shared__ float As[8][128];
    __shared__ float Bs[8][128];

    int tid = threadIdx.x;
    int ty = tid >> 4, tx = tid & 15;
    int lr = tid >> 1;
    int lc = (tid & 1) << 2;
    int bm = blockIdx.y << 7;
    int bn = blockIdx.x << 7;

    int ar = bm + lr;
    int arc = ar < M ? ar : (M - 1);
    const float* Arow = g_Y + (size_t)arc * EMB;
    const float* Brow = Wo + (size_t)(bn + lr) * EMB;

    ull acc2[4][8];
#pragma unroll
    for (int i = 0; i < 4; i++)
#pragma unroll
        for (int j = 0; j < 8; j++) acc2[i][j] = 0ull;

    for (int k0 = 0; k0 < EMB; k0 += 8) {
        float4 a4 = *(const float4*)(Arow + k0 + lc);
        float4 b4 = *(const float4*)(Brow + k0 + lc);
        __syncthreads();
        As[lc+0][lr] = a4.x; As[lc+1][lr] = a4.y; As[lc+2][lr] = a4.z; As[lc+3][lr] = a4.w;
        Bs[lc+0][lr] = b4.x; Bs[lc+1][lr] = b4.y; Bs[lc+2][lr] = b4.z; Bs[lc+3][lr] = b4.w;
        __syncthreads();
#pragma unroll
        for (int k = 0; k < 8; k++) {
            ulonglong2 a01 = *(const ulonglong2*)&As[k][ty*4];
            ulonglong2 a23 = *(const ulonglong2*)&As[k][64 + ty*4];
            float4 b0 = *(const float4*)&Bs[k][tx*4];
            float4 b1 = *(const float4*)&Bs[k][64 + tx*4];
            ull a2[4] = {a01.x, a01.y, a23.x, a23.y};
            ull bb[8] = {pk2(b0.x,b0.x), pk2(b0.y,b0.y), pk2(b0.z,b0.z), pk2(b0.w,b0.w),
                         pk2(b1.x,b1.x), pk2(b1.y,b1.y), pk2(b1.z,b1.z), pk2(b1.w,b1.w)};
#pragma unroll
            for (int i = 0; i < 4; i++)
#pragma unroll
                for (int j = 0; j < 8; j++)
                    fma2(acc2[i][j], a2[i], bb[j]);
        }
    }

#pragma unroll
    for (int p = 0; p < 4; p++) {
        int rbase = (p < 2) ? (bm + ty*4 + 2*p) : (bm + 64 + ty*4 + 2*(p-2));
#pragma unroll
        for (int j = 0; j < 8; j++) {
            int col = bn + ((j < 4) ? tx*4 + j : 64 + tx*4 + (j-4));
            float2 v = upk(acc2[p][j]);
            float bv_ = bo[col];
            if (rbase < M)     out[(size_t)rbase * EMB + col]     = v.x + bv_;
            if (rbase + 1 < M) out[(size_t)(rbase+1) * EMB + col] = v.y + bv_;
        }
    }
}

// ---------------------------------------------------------------------------
// c projection: g_C[b,:] = x[b,0,:] @ Wc^T + bc
// ---------------------------------------------------------------------------
__global__ void cproj_kernel(const float* __restrict__ x,
                             const float* __restrict__ Wc,
                             const float* __restrict__ bc)
{
    int b = blockIdx.x;
    __shared__ float xs[EMB];
    for (int e = threadIdx.x; e < EMB; e += blockDim.x)
        xs[e] = x[(size_t)b * SFULL * EMB + e];
    __syncthreads();
    for (int j = threadIdx.x; j < EMB; j += blockDim.x) {
        const float* w = Wc + (size_t)j * EMB;
        float acc = bc[j];
        for (int e = 0; e < EMB; e++) acc += xs[e] * w[e];
        g_C[b * EMB + j] = acc;
    }
}

// ---------------------------------------------------------------------------
// Per-(b,h,t) coefficients. y==0: coef from Q; y==1: ck from K.
// ---------------------------------------------------------------------------
__global__ __launch_bounds__(256) void coef_kernel()
{
    int gw = blockIdx.x * 8 + (threadIdx.x >> 5);
    int lane = threadIdx.x & 31;
    int q = gw & (SEQ - 1);
    int bh = gw >> 10;
    int b = bh / NH, h = bh % NH;
    const float* src = (blockIdx.y == 0) ? g_Q : g_K;
    const float* qp = src + (size_t)(b * SEQ + q) * EMB + h * HD;
    const float* cp = g_C + b * EMB + h * HD;
    float q0 = qp[lane], q1 = qp[lane + 32];
    float c0 = cp[lane], c1 = cp[lane + 32];
    float qn = q0*q0 + q1*q1;
    float cq = c0*q0 + c1*q1;
    float cn = c0*c0 + c1*c1;
#pragma unroll
    for (int o = 16; o; o >>= 1) {
        qn += __shfl_xor_sync(0xffffffffu, qn, o);
        cq += __shfl_xor_sync(0xffffffffu, cq, o);
        cn += __shfl_xor_sync(0xffffffffu, cn, o);
    }
    if (lane == 0) {
        float cn2 = fmaxf(cn, 1e-5f);
        if (blockIdx.y == 0) {
            float qn2 = fmaxf(qn, 1e-5f);
            g_coef[gw] = cq / (qn2 * sqrtf(64.0f * cn2));
        } else {
            g_ck[gw] = cq / sqrtf(64.0f * cn2);
        }
    }
}

// ---------------------------------------------------------------------------
// Score GEMM: logits[bh, q, k] = (q . k) * coef[bh,q] (f32x2)
// per bh: M=N=1024, K=64. 128x128x8 tiles.
// ---------------------------------------------------------------------------
__global__ __launch_bounds__(256) void score_gemm(float* __restrict__ attn)
{
    int bh = blockIdx.z;
    int b = bh / NH, h = bh % NH;
    const float* Qb = g_Q + (size_t)b * SEQ * EMB + h * HD;
    const float* Kb = g_K + (size_t)b * SEQ * EMB + h * HD;
    float* Cb = attn + (size_t)bh * SEQ * SEQ;
    const float* coefp = g_coef + bh * SEQ;

    __shared__ float As[8][128];
    __shared__ float Bs[8][128];

    int tid = threadIdx.x;
    int ty = tid >> 4, tx = tid & 15;
    int lr = tid >> 1;
    int lc = (tid & 1) << 2;
    int bm = blockIdx.y << 7;
    int bn = blockIdx.x << 7;

    const float* Arow = Qb + (size_t)(bm + lr) * EMB;
    const float* Brow = Kb + (size_t)(bn + lr) * EMB;

    ull acc2[4][8];
#pragma unroll
    for (int i = 0; i < 4; i++)
#pragma unroll
        for (int j = 0; j < 8; j++) acc2[i][j] = 0ull;

    for (int k0 = 0; k0 < HD; k0 += 8) {
        float4 a4 = *(const float4*)(Arow + k0 + lc);
        float4 b4 = *(const float4*)(Brow + k0 + lc);
        __syncthreads();
        As[lc+0][lr] = a4.x; As[lc+1][lr] = a4.y; As[lc+2][lr] = a4.z; As[lc+3][lr] = a4.w;
        Bs[lc+0][lr] = b4.x; Bs[lc+1][lr] = b4.y; Bs[lc+2][lr] = b4.z; Bs[lc+3][lr] = b4.w;
        __syncthreads();
#pragma unroll
        for (int k = 0; k < 8; k++) {
            ulonglong2 a01 = *(const ulonglong2*)&As[k][ty*4];
            ulonglong2 a23 = *(const ulonglong2*)&As[k][64 + ty*4];
            float4 b0 = *(const float4*)&Bs[k][tx*4];
            float4 b1 = *(const float4*)&Bs[k][64 + tx*4];
            ull a2[4] = {a01.x, a01.y, a23.x, a23.y};
            ull bb[8] = {pk2(b0.x,b0.x), pk2(b0.y,b0.y), pk2(b0.z,b0.z), pk2(b0.w,b0.w),
                         pk2(b1.x,b1.x), pk2(b1.y,b1.y), pk2(b1.z,b1.z), pk2(b1.w,b1.w)};
#pragma unroll
            for (int i = 0; i < 4; i++)
#pragma unroll
                for (int j = 0; j < 8; j++)
                    fma2(acc2[i][j], a2[i], bb[j]);
        }
    }

#pragma unroll
    for (int p = 0; p < 4; p++) {
        int rbase = (p < 2) ? (bm + ty*4 + 2*p) : (bm + 64 + ty*4 + 2*(p-2));
        float cf0 = coefp[rbase], cf1 = coefp[rbase+1];
        float* crow0 = Cb + (size_t)rbase * SEQ;
        float* crow1 = Cb + (size_t)(rbase+1) * SEQ;
#pragma unroll
        for (int j = 0; j < 8; j++) {
            int col = bn + ((j < 4) ? tx*4 + j : 64 + tx*4 + (j-4));
            float2 v = upk(acc2[p][j]);
            crow0[col] = v.x * cf0;
            crow1[col] = v.y * cf1;
        }
    }
}

// ---------------------------------------------------------------------------
// In-place row softmax over attn rows of length 1024.
// ---------------------------------------------------------------------------
__global__ __launch_bounds__(256) void softmax_kernel(float* __restrict__ attn)
{
    size_t row = blockIdx.x;
    float4* p = (float4*)(attn + row * SEQ);
    int t = threadIdx.x;
    int wid = t >> 5, lane = t & 31;
    __shared__ float redm[8], reds[8];

    float4 v = p[t];
    float m = fmaxf(fmaxf(v.x, v.y), fmaxf(v.z, v.w));
#pragma unroll
    for (int o = 16; o; o >>= 1) m = fmaxf(m, __shfl_xor_sync(0xffffffffu, m, o));
    if (lane == 0) redm[wid] = m;
    __syncthreads();
    m = redm[0];
#pragma unroll
    for (int i = 1; i < 8; i++) m = fmaxf(m, redm[i]);

    v.x = __expf(v.x - m); v.y = __expf(v.y - m);
    v.z = __expf(v.z - m); v.w = __expf(v.w - m);
    float s = v.x + v.y + v.z + v.w;
#pragma unroll
    for (int o = 16; o; o >>= 1) s += __shfl_xor_sync(0xffffffffu, s, o);
    if (lane == 0) reds[wid] = s;
    __syncthreads();
    s = reds[0];
#pragma unroll
    for (int i = 1; i < 8; i++) s += reds[i];

    float inv = 1.0f / s;
    v.x *= inv; v.y *= inv; v.z *= inv; v.w *= inv;
    p[t] = v;
}

// ---------------------------------------------------------------------------
// values = attn @ V  per (b,h): M=1024, N=64, K=1024.
// 128x64 tile, 256 threads (16x16), 8 rows x 4 cols per thread, f32x2.
// ---------------------------------------------------------------------------
__global__ __launch_bounds__(256) void av_gemm(const float* __restrict__ attn)
{
    int bh = blockIdx.y;
    int b = bh / NH, h = bh % NH;
    const float* Ab = attn + (size_t)bh * SEQ * SEQ;
    const float* Vb = g_V + (size_t)b * SEQ * EMB + h * HD;
    int bm = blockIdx.x << 7;

    __shared__ float As[16][128];
    __shared__ float Bs[16][64];

    int tid = threadIdx.x;
    int ty = tid >> 4, tx = tid & 15;   // ty: row group (8 rows), tx: col group (4 cols)
    int a_r = tid >> 1;                 // 0..127
    int a_c = (tid & 1) << 3;           // 0 or 8
    int b_r = tid >> 4;                 // 0..15
    int b_c = (tid & 15) << 2;          // 0..60

    const float* Arow = Ab + (size_t)(bm + a_r) * SEQ;

    ull acc2[4][4];
#pragma unroll
    for (int i = 0; i < 4; i++)
#pragma unroll
        for (int j = 0; j < 4; j++) acc2[i][j] = 0ull;

    for (int k0 = 0; k0 < SEQ; k0 += 16) {
        float4 a4a = *(const float4*)(Arow + k0 + a_c);
        float4 a4b = *(const float4*)(Arow + k0 + a_c + 4);
        float4 b4  = *(const float4*)(Vb + (size_t)(k0 + b_r) * EMB + b_c);
        __syncthreads();
        As[a_c+0][a_r] = a4a.x; As[a_c+1][a_r] = a4a.y;
        As[a_c+2][a_r] = a4a.z; As[a_c+3][a_r] = a4a.w;
        As[a_c+4][a_r] = a4b.x; As[a_c+5][a_r] = a4b.y;
        As[a_c+6][a_r] = a4b.z; As[a_c+7][a_r] = a4b.w;
        *(float4*)&Bs[b_r][b_c] = b4;
        __syncthreads();
#pragma unroll
        for (int k = 0; k < 16; k++) {
            ulonglong2 a01 = *(const ulonglong2*)&As[k][ty*8];
            ulonglong2 a23 = *(const ulonglong2*)&As[k][ty*8 + 4];
            float4 b4r = *(const float4*)&Bs[k][tx*4];
            ull a2[4] = {a01.x, a01.y, a23.x, a23.y};
            ull bb[4] = {pk2(b4r.x,b4r.x), pk2(b4r.y,b4r.y), pk2(b4r.z,b4r.z), pk2(b4r.w,b4r.w)};
#pragma unroll
            for (int i = 0; i < 4; i++)
#pragma unroll
                for (int j = 0; j < 4; j++)
                    fma2(acc2[i][j], a2[i], bb[j]);
        }
    }

#pragma unroll
    for (int p = 0; p < 4; p++) {
        int row = bm + ty*8 + 2*p;
        float* crow0 = g_Y + (size_t)(b * SFULL + 1 + row) * EMB + h * HD;
        float* crow1 = g_Y + (size_t)(b * SFULL + 2 + row) * EMB + h * HD;
#pragma unroll
        for (int j = 0; j < 4; j++) {
            float2 v = upk(acc2[p][j]);
            crow0[tx*4 + j] = v.x;
            crow1[tx*4 + j] = v.y;
        }
    }
}

// ---------------------------------------------------------------------------
// CLS row: g_Y[b,0,:] = 0.5*(cls_token + sum_k ck[b,h,k]*V[b,k,h,:])
// ---------------------------------------------------------------------------
__global__ void cls_kernel(const float* __restrict__ x)
{
    int bh = blockIdx.x;
    int b = bh / NH, h = bh % NH;
    int d = threadIdx.x;  // 64 threads
    __shared__ float cks[SEQ];
    for (int k = d; k < SEQ; k += 64) cks[k] = g_ck[bh * SEQ + k];
    __syncthreads();
    const float* V = g_V + (size_t)b * SEQ * EMB + h * HD + d;
    float acc = 0.f;
#pragma unroll 8
    for (int k = 0; k < SEQ; k++) acc += cks[k] * V[(size_t)k * EMB];
    float cls = x[(size_t)b * SFULL * EMB + h * HD + d];
    g_Y[(size_t)b * SFULL * EMB + h * HD + d] = 0.5f * (cls + acc);
}

// ---------------------------------------------------------------------------

extern "C" void kernel_launch(void* const* d_in, const int* in_sizes, int n_in,
                              void* d_out, int out_size)
{
    const float* x  = (const float*)d_in[0];
    const float* Wq = (const float*)d_in[1]; const float* bq = (const float*)d_in[2];
    const float* Wk = (const float*)d_in[3]; const float* bk = (const float*)d_in[4];
    const float* Wv = (const float*)d_in[5]; const float* bv = (const float*)d_in[6];
    const float* Wc = (const float*)d_in[7]; const float* bc = (const float*)d_in[8];
    const float* Wo = (const float*)d_in[9]; const float* bo = (const float*)d_in[10];

    float* out  = (float*)d_out;
    float* attn = out + (size_t)NB * SFULL * EMB;

    qkv_gemm<<<dim3(6, 64, 3), 256>>>(x, Wq, bq, Wk, bk, Wv, bv);
    cproj_kernel<<<8, 256>>>(x, Wc, bc);
    coef_kernel<<<dim3(12288, 2), 256>>>();
    score_gemm<<<dim3(8, 8, 96), 256>>>(attn);
    softmax_kernel<<<BH * SEQ, 256>>>(attn);
    av_gemm<<<dim3(8, 96), 256>>>(attn);
    cls_kernel<<<96, 64>>>(x);
    out_gemm<<<dim3(6, 65), 256>>>(Wo, bo, out);
}

// round 4
// speedup vs baseline: 1.2358x; 1.2358x over previous
#include <cuda_runtime.h>
#include <cuda_bf16.h>

#define NB 8
#define SEQ 1024
#define SFULL 1025
#define EMB 768
#define NH 12
#define HD 64
#define BH (NB*NH)   // 96
#define MOUT (NB*SFULL) // 8200

typedef unsigned u32;
typedef __nv_bfloat16 bf16;
typedef __nv_bfloat162 bf162;

// ---------------- static scratch ----------------
__device__ float g_Q[NB*SEQ*EMB];
__device__ float g_K[NB*SEQ*EMB];
__device__ float g_V[NB*SEQ*EMB];
__device__ float g_C[NB*EMB];
__device__ float g_coef[BH*SEQ];
__device__ float g_ck[BH*SEQ];

__device__ bf16 g_xh[NB*SFULL*EMB], g_xl[NB*SFULL*EMB];
__device__ bf16 g_Wqh[EMB*EMB], g_Wql[EMB*EMB];
__device__ bf16 g_Wkh[EMB*EMB], g_Wkl[EMB*EMB];
__device__ bf16 g_Wvh[EMB*EMB], g_Wvl[EMB*EMB];
__device__ bf16 g_Woh[EMB*EMB], g_Wol[EMB*EMB];
__device__ bf16 g_Qh[NB*SEQ*EMB], g_Ql[NB*SEQ*EMB];
__device__ bf16 g_Kh[NB*SEQ*EMB], g_Kl[NB*SEQ*EMB];
__device__ bf16 g_Vh[NB*SEQ*EMB], g_Vl[NB*SEQ*EMB];
__device__ bf16 g_Ah[(size_t)BH*SEQ*SEQ], g_Al[(size_t)BH*SEQ*SEQ];
__device__ bf16 g_Yh[NB*SFULL*EMB], g_Yl[NB*SFULL*EMB];

// ---------------- helpers ----------------
__device__ __forceinline__ void mma_bf16(float* d, const u32* a, const u32* b) {
    asm("mma.sync.aligned.m16n8k16.row.col.f32.bf16.bf16.f32 "
        "{%0,%1,%2,%3},{%4,%5,%6,%7},{%8,%9},{%0,%1,%2,%3};"
        : "+f"(d[0]), "+f"(d[1]), "+f"(d[2]), "+f"(d[3])
        : "r"(a[0]), "r"(a[1]), "r"(a[2]), "r"(a[3]), "r"(b[0]), "r"(b[1]));
}
// swizzled smem index (stride 24 bf16/row, XOR 8-col halves by row bit3)
__device__ __forceinline__ int sx(int r, int c) { return r*24 + (c ^ (((r>>3)&1)<<3)); }
__device__ __forceinline__ int px(int r, int c) { return r*24 + c; }   // plain

__device__ __forceinline__ void split1(float v, bf16& h, bf16& l) {
    h = __float2bfloat16(v);
    l = __float2bfloat16(v - __bfloat162float(h));
}

// warp-level 3-term bf16 mma over MT m16-tiles x NT n8-tiles.  SWB: swizzled B smem.
template<int MT, int NT, bool SWB>
__device__ __forceinline__ void warp_mma3(
    float acc[MT][NT][4],
    const bf16* SAh, const bf16* SAl, const bf16* SBh, const bf16* SBl,
    int rbase, int cbase, int gid, int tig)
{
    u32 Ah[MT][4], Al[MT][4];
#pragma unroll
    for (int i = 0; i < MT; i++) {
        int r = rbase + 16*i + gid;
        Ah[i][0] = *(const u32*)&SAh[sx(r,   2*tig)];
        Ah[i][1] = *(const u32*)&SAh[sx(r+8, 2*tig)];
        Ah[i][2] = *(const u32*)&SAh[sx(r,   2*tig+8)];
        Ah[i][3] = *(const u32*)&SAh[sx(r+8, 2*tig+8)];
        Al[i][0] = *(const u32*)&SAl[sx(r,   2*tig)];
        Al[i][1] = *(const u32*)&SAl[sx(r+8, 2*tig)];
        Al[i][2] = *(const u32*)&SAl[sx(r,   2*tig+8)];
        Al[i][3] = *(const u32*)&SAl[sx(r+8, 2*tig+8)];
    }
    u32 Bh[NT][2], Bl[NT][2];
#pragma unroll
    for (int j = 0; j < NT; j++) {
        int n = cbase + 8*j + gid;
        int i0 = SWB ? sx(n, 2*tig)   : px(n, 2*tig);
        int i1 = SWB ? sx(n, 2*tig+8) : px(n, 2*tig+8);
        Bh[j][0] = *(const u32*)&SBh[i0];
        Bh[j][1] = *(const u32*)&SBh[i1];
        Bl[j][0] = *(const u32*)&SBl[i0];
        Bl[j][1] = *(const u32*)&SBl[i1];
    }
#pragma unroll
    for (int i = 0; i < MT; i++)
#pragma unroll
        for (int j = 0; j < NT; j++) {
            mma_bf16(acc[i][j], Ah[i], Bh[j]);
            mma_bf16(acc[i][j], Ah[i], Bl[j]);
            mma_bf16(acc[i][j], Al[i], Bh[j]);
        }
}

// ---------------- split conversion ----------------
__global__ __launch_bounds__(256) void convert_split(const float* __restrict__ src, int tag, int n4)
{
    int i = blockIdx.x * 256 + threadIdx.x;
    if (i >= n4) return;
    bf16 *h, *l;
    if (tag == 0)      { h = g_xh;  l = g_xl;  }
    else if (tag == 1) { h = g_Wqh; l = g_Wql; }
    else if (tag == 2) { h = g_Wkh; l = g_Wkl; }
    else if (tag == 3) { h = g_Wvh; l = g_Wvl; }
    else               { h = g_Woh; l = g_Wol; }
    float4 v = ((const float4*)src)[i];
    bf16 h0,l0,h1,l1,h2,l2,h3,l3;
    split1(v.x,h0,l0); split1(v.y,h1,l1); split1(v.z,h2,l2); split1(v.w,h3,l3);
    bf162 hh0; hh0.x=h0; hh0.y=h1;  bf162 hh1; hh1.x=h2; hh1.y=h3;
    bf162 ll0; ll0.x=l0; ll0.y=l1;  bf162 ll1; ll1.x=l2; ll1.y=l3;
    ((bf162*)h)[2*i] = hh0; ((bf162*)h)[2*i+1] = hh1;
    ((bf162*)l)[2*i] = ll0; ((bf162*)l)[2*i+1] = ll1;
}

// ---------------- QKV projection (tensor) ----------------
// C[8192,768] = xt @ W^T + b.  128x128 tile, K=768 (48 steps).
__global__ __launch_bounds__(256,1) void qkv_tc(
    const float* __restrict__ bq, const float* __restrict__ bk, const float* __restrict__ bv)
{
    const bf16 *Wh, *Wl; const float* bias; float* Cf; bf16 *Ch, *Cl;
    int z = blockIdx.z;
    if (z == 0)      { Wh=g_Wqh; Wl=g_Wql; bias=bq; Cf=g_Q; Ch=g_Qh; Cl=g_Ql; }
    else if (z == 1) { Wh=g_Wkh; Wl=g_Wkl; bias=bk; Cf=g_K; Ch=g_Kh; Cl=g_Kl; }
    else             { Wh=g_Wvh; Wl=g_Wvl; bias=bv; Cf=g_V; Ch=g_Vh; Cl=g_Vl; }

    __shared__ bf16 SAh[128*24], SAl[128*24], SBh[128*24], SBl[128*24];
    int tid = threadIdx.x;
    int lane = tid & 31, wid = tid >> 5;
    int gid = lane >> 2, tig = lane & 3;
    int wm = wid >> 1, wn = wid & 1;
    int bm = blockIdx.y, bn = blockIdx.x;

    int arow = tid >> 1, ahalf = (tid & 1) << 3;
    int grow = bm*128 + arow;
    size_t aoff = (size_t)((grow>>10)*SFULL + 1 + (grow&1023)) * EMB + ahalf;
    size_t boff = (size_t)(bn*128 + arow) * EMB + ahalf;

    float acc[2][8][4];
#pragma unroll
    for (int i=0;i<2;i++)
#pragma unroll
        for (int j=0;j<8;j++)
#pragma unroll
            for (int q=0;q<4;q++) acc[i][j][q]=0.f;

    uint4 rAh = *(const uint4*)(g_xh + aoff);
    uint4 rAl = *(const uint4*)(g_xl + aoff);
    uint4 rBh = *(const uint4*)(Wh + boff);
    uint4 rBl = *(const uint4*)(Wl + boff);

    const int NK = EMB/16;
    for (int ks = 0; ks < NK; ks++) {
        if (ks) __syncthreads();
        *(uint4*)&SAh[sx(arow, ahalf)] = rAh;
        *(uint4*)&SAl[sx(arow, ahalf)] = rAl;
        *(uint4*)&SBh[sx(arow, ahalf)] = rBh;
        *(uint4*)&SBl[sx(arow, ahalf)] = rBl;
        __syncthreads();
        if (ks+1 < NK) {
            size_t k2 = (size_t)(ks+1)*16;
            rAh = *(const uint4*)(g_xh + aoff + k2);
            rAl = *(const uint4*)(g_xl + aoff + k2);
            rBh = *(const uint4*)(Wh + boff + k2);
            rBl = *(const uint4*)(Wl + boff + k2);
        }
        warp_mma3<2,8,true>(acc, SAh, SAl, SBh, SBl, wm*32, wn*64, gid, tig);
    }

#pragma unroll
    for (int i=0;i<2;i++) {
        int row0 = bm*128 + wm*32 + 16*i + gid;
#pragma unroll
        for (int j=0;j<8;j++) {
            int col0 = bn*128 + wn*64 + 8*j + 2*tig;
            float2 bv2 = *(const float2*)(bias + col0);
            float v0 = acc[i][j][0]+bv2.x, v1 = acc[i][j][1]+bv2.y;
            float v2 = acc[i][j][2]+bv2.x, v3 = acc[i][j][3]+bv2.y;
            size_t o0 = (size_t)row0*EMB + col0, o8 = (size_t)(row0+8)*EMB + col0;
            *(float2*)(Cf+o0) = make_float2(v0,v1);
            *(float2*)(Cf+o8) = make_float2(v2,v3);
            bf16 h,l; bf162 th, tl;
            split1(v0,h,l); th.x=h; tl.x=l; split1(v1,h,l); th.y=h; tl.y=l;
            *(bf162*)(Ch+o0)=th; *(bf162*)(Cl+o0)=tl;
            split1(v2,h,l); th.x=h; tl.x=l; split1(v3,h,l); th.y=h; tl.y=l;
            *(bf162*)(Ch+o8)=th; *(bf162*)(Cl+o8)=tl;
        }
    }
}

// ---------------- out projection (tensor) ----------------
__global__ __launch_bounds__(256,1) void out_tc(const float* __restrict__ bo, float* __restrict__ out)
{
    __shared__ bf16 SAh[128*24], SAl[128*24], SBh[128*24], SBl[128*24];
    int tid = threadIdx.x;
    int lane = tid & 31, wid = tid >> 5;
    int gid = lane >> 2, tig = lane & 3;
    int wm = wid >> 1, wn = wid & 1;
    int bm = blockIdx.y, bn = blockIdx.x;

    int arow = tid >> 1, ahalf = (tid & 1) << 3;
    int grow = bm*128 + arow; if (grow >= MOUT) grow = MOUT-1;
    size_t aoff = (size_t)grow * EMB + ahalf;
    size_t boff = (size_t)(bn*128 + arow) * EMB + ahalf;

    float acc[2][8][4];
#pragma unroll
    for (int i=0;i<2;i++)
#pragma unroll
        for (int j=0;j<8;j++)
#pragma unroll
            for (int q=0;q<4;q++) acc[i][j][q]=0.f;

    uint4 rAh = *(const uint4*)(g_Yh + aoff);
    uint4 rAl = *(const uint4*)(g_Yl + aoff);
    uint4 rBh = *(const uint4*)(g_Woh + boff);
    uint4 rBl = *(const uint4*)(g_Wol + boff);

    const int NK = EMB/16;
    for (int ks = 0; ks < NK; ks++) {
        if (ks) __syncthreads();
        *(uint4*)&SAh[sx(arow, ahalf)] = rAh;
        *(uint4*)&SAl[sx(arow, ahalf)] = rAl;
        *(uint4*)&SBh[sx(arow, ahalf)] = rBh;
        *(uint4*)&SBl[sx(arow, ahalf)] = rBl;
        __syncthreads();
        if (ks+1 < NK) {
            size_t k2 = (size_t)(ks+1)*16;
            rAh = *(const uint4*)(g_Yh + aoff + k2);
            rAl = *(const uint4*)(g_Yl + aoff + k2);
            rBh = *(const uint4*)(g_Woh + boff + k2);
            rBl = *(const uint4*)(g_Wol + boff + k2);
        }
        warp_mma3<2,8,true>(acc, SAh, SAl, SBh, SBl, wm*32, wn*64, gid, tig);
    }

#pragma unroll
    for (int i=0;i<2;i++) {
        int row0 = bm*128 + wm*32 + 16*i + gid;
#pragma unroll
        for (int j=0;j<8;j++) {
            int col0 = bn*128 + wn*64 + 8*j + 2*tig;
            float2 bv2 = *(const float2*)(bo + col0);
            if (row0 < MOUT)
                *(float2*)(out + (size_t)row0*EMB + col0) =
                    make_float2(acc[i][j][0]+bv2.x, acc[i][j][1]+bv2.y);
            if (row0+8 < MOUT)
                *(float2*)(out + (size_t)(row0+8)*EMB + col0) =
                    make_float2(acc[i][j][2]+bv2.x, acc[i][j][3]+bv2.y);
        }
    }
}

// ---------------- score (tensor) ----------------
// logits[bh,q,k] = (Q.K)*coef[q] per bh; M=N=1024, K=64 (4 steps).
__global__ __launch_bounds__(256,1) void score_tc(float* __restrict__ attn)
{
    int bh = blockIdx.z;
    int b = bh / NH, h = bh % NH;
    __shared__ bf16 SAh[128*24], SAl[128*24], SBh[128*24], SBl[128*24];
    int tid = threadIdx.x;
    int lane = tid & 31, wid = tid >> 5;
    int gid = lane >> 2, tig = lane & 3;
    int wm = wid >> 1, wn = wid & 1;
    int bm = blockIdx.y, bn = blockIdx.x;

    int arow = tid >> 1, ahalf = (tid & 1) << 3;
    size_t aoff = (size_t)(b*SEQ + bm*128 + arow)*EMB + h*HD + ahalf;
    size_t boff = (size_t)(b*SEQ + bn*128 + arow)*EMB + h*HD + ahalf;

    float acc[2][8][4];
#pragma unroll
    for (int i=0;i<2;i++)
#pragma unroll
        for (int j=0;j<8;j++)
#pragma unroll
            for (int q=0;q<4;q++) acc[i][j][q]=0.f;

    uint4 rAh = *(const uint4*)(g_Qh + aoff);
    uint4 rAl = *(const uint4*)(g_Ql + aoff);
    uint4 rBh = *(const uint4*)(g_Kh + boff);
    uint4 rBl = *(const uint4*)(g_Kl + boff);

    const int NK = HD/16;
    for (int ks = 0; ks < NK; ks++) {
        if (ks) __syncthreads();
        *(uint4*)&SAh[sx(arow, ahalf)] = rAh;
        *(uint4*)&SAl[sx(arow, ahalf)] = rAl;
        *(uint4*)&SBh[sx(arow, ahalf)] = rBh;
        *(uint4*)&SBl[sx(arow, ahalf)] = rBl;
        __syncthreads();
        if (ks+1 < NK) {
            size_t k2 = (size_t)(ks+1)*16;
            rAh = *(const uint4*)(g_Qh + aoff + k2);
            rAl = *(const uint4*)(g_Ql + aoff + k2);
            rBh = *(const uint4*)(g_Kh + boff + k2);
            rBl = *(const uint4*)(g_Kl + boff + k2);
        }
        warp_mma3<2,8,true>(acc, SAh, SAl, SBh, SBl, wm*32, wn*64, gid, tig);
    }

    float* Cb = attn + (size_t)bh*SEQ*SEQ;
    const float* coefp = g_coef + bh*SEQ;
#pragma unroll
    for (int i=0;i<2;i++) {
        int row0 = bm*128 + wm*32 + 16*i + gid;
        float cf0 = coefp[row0], cf8 = coefp[row0+8];
#pragma unroll
        for (int j=0;j<8;j++) {
            int col0 = bn*128 + wn*64 + 8*j + 2*tig;
            *(float2*)(Cb + (size_t)row0*SEQ + col0) =
                make_float2(acc[i][j][0]*cf0, acc[i][j][1]*cf0);
            *(float2*)(Cb + (size_t)(row0+8)*SEQ + col0) =
                make_float2(acc[i][j][2]*cf8, acc[i][j][3]*cf8);
        }
    }
}

// ---------------- attn @ V (tensor) ----------------
// per bh: M=1024, N=64, K=1024 (64 steps). CTA 128x64, V^T staged in smem.
__global__ __launch_bounds__(256,1) void av_tc()
{
    int bh = blockIdx.y;
    int b = bh / NH, h = bh % NH;
    __shared__ bf16 SAh[128*24], SAl[128*24], SBTh[64*24], SBTl[64*24];
    int tid = threadIdx.x;
    int lane = tid & 31, wid = tid >> 5;
    int gid = lane >> 2, tig = lane & 3;
    int wm = wid >> 1, wn = wid & 1;
    int bm = blockIdx.x;

    int arow = tid >> 1, ahalf = (tid & 1) << 3;
    size_t aoff = (size_t)(bh*SEQ + bm*128 + arow)*SEQ + ahalf;

    int tv = tid & 127;
    int vk = tv >> 3, vd0 = (tv & 7) << 3;
    const bf16* Vsrc = (tid < 128) ? g_Vh : g_Vl;
    bf16* SBT = (tid < 128) ? SBTh : SBTl;
    size_t voff = (size_t)(b*SEQ + vk)*EMB + h*HD + vd0;

    float acc[2][4][4];
#pragma unroll
    for (int i=0;i<2;i++)
#pragma unroll
        for (int j=0;j<4;j++)
#pragma unroll
            for (int q=0;q<4;q++) acc[i][j][q]=0.f;

    uint4 rAh = *(const uint4*)(g_Ah + aoff);
    uint4 rAl = *(const uint4*)(g_Al + aoff);
    uint4 rV  = *(const uint4*)(Vsrc + voff);

    const int NK = SEQ/16;
    for (int ks = 0; ks < NK; ks++) {
        if (ks) __syncthreads();
        *(uint4*)&SAh[sx(arow, ahalf)] = rAh;
        *(uint4*)&SAl[sx(arow, ahalf)] = rAl;
        {   // transpose V slice: SBT[d][k]
            bf16 ev[8]; *(uint4*)ev = rV;
#pragma unroll
            for (int e=0;e<8;e++) SBT[(vd0+e)*24 + vk] = ev[e];
        }
        __syncthreads();
        if (ks+1 < NK) {
            rAh = *(const uint4*)(g_Ah + aoff + (ks+1)*16);
            rAl = *(const uint4*)(g_Al + aoff + (ks+1)*16);
            rV  = *(const uint4*)(Vsrc + voff + (size_t)(ks+1)*16*EMB);
        }
        warp_mma3<2,4,false>(acc, SAh, SAl, SBTh, SBTl, wm*32, wn*32, gid, tig);
    }

#pragma unroll
    for (int i=0;i<2;i++) {
        int row0 = bm*128 + wm*32 + 16*i + gid;
#pragma unroll
        for (int j=0;j<4;j++) {
            int col0 = wn*32 + 8*j + 2*tig;
            size_t o0 = (size_t)(b*SFULL + 1 + row0)*EMB + h*HD + col0;
            size_t o8 = (size_t)(b*SFULL + 9 + row0)*EMB + h*HD + col0;
            bf16 hh,ll; bf162 th, tl;
            split1(acc[i][j][0],hh,ll); th.x=hh; tl.x=ll;
            split1(acc[i][j][1],hh,ll); th.y=hh; tl.y=ll;
            *(bf162*)(g_Yh+o0)=th; *(bf162*)(g_Yl+o0)=tl;
            split1(acc[i][j][2],hh,ll); th.x=hh; tl.x=ll;
            split1(acc[i][j][3],hh,ll); th.y=hh; tl.y=ll;
            *(bf162*)(g_Yh+o8)=th; *(bf162*)(g_Yl+o8)=tl;
        }
    }
}

// ---------------- c projection ----------------
__global__ void cproj_kernel(const float* __restrict__ x,
                             const float* __restrict__ Wc,
                             const float* __restrict__ bc)
{
    int b = blockIdx.x;
    __shared__ float xs[EMB];
    for (int e = threadIdx.x; e < EMB; e += blockDim.x)
        xs[e] = x[(size_t)b * SFULL * EMB + e];
    __syncthreads();
    for (int j = threadIdx.x; j < EMB; j += blockDim.x) {
        const float* w = Wc + (size_t)j * EMB;
        float acc = bc[j];
        for (int e = 0; e < EMB; e++) acc += xs[e] * w[e];
        g_C[b * EMB + j] = acc;
    }
}

// ---------------- coefficients ----------------
__global__ __launch_bounds__(256) void coef_kernel()
{
    int gw = blockIdx.x * 8 + (threadIdx.x >> 5);
    int lane = threadIdx.x & 31;
    int q = gw & (SEQ - 1);
    int bh = gw >> 10;
    int b = bh / NH, h = bh % NH;
    const float* src = (blockIdx.y == 0) ? g_Q : g_K;
    const float* qp = src + (size_t)(b * SEQ + q) * EMB + h * HD;
    const float* cp = g_C + b * EMB + h * HD;
    float q0 = qp[lane], q1 = qp[lane + 32];
    float c0 = cp[lane], c1 = cp[lane + 32];
    float qn = q0*q0 + q1*q1;
    float cq = c0*q0 + c1*q1;
    float cn = c0*c0 + c1*c1;
#pragma unroll
    for (int o = 16; o; o >>= 1) {
        qn += __shfl_xor_sync(0xffffffffu, qn, o);
        cq += __shfl_xor_sync(0xffffffffu, cq, o);
        cn += __shfl_xor_sync(0xffffffffu, cn, o);
    }
    if (lane == 0) {
        float cn2 = fmaxf(cn, 1e-5f);
        if (blockIdx.y == 0) {
            float qn2 = fmaxf(qn, 1e-5f);
            g_coef[gw] = cq / (qn2 * sqrtf(64.0f * cn2));
        } else {
            g_ck[gw] = cq / sqrtf(64.0f * cn2);
        }
    }
}

// ---------------- softmax (fp32 in-place + bf16 split out) ----------------
__global__ __launch_bounds__(256) void softmax_kernel(float* __restrict__ attn)
{
    size_t row = blockIdx.x;
    float4* p = (float4*)(attn + row * SEQ);
    int t = threadIdx.x;
    int wid = t >> 5, lane = t & 31;
    __shared__ float redm[8], reds[8];

    float4 v = p[t];
    float m = fmaxf(fmaxf(v.x, v.y), fmaxf(v.z, v.w));
#pragma unroll
    for (int o = 16; o; o >>= 1) m = fmaxf(m, __shfl_xor_sync(0xffffffffu, m, o));
    if (lane == 0) redm[wid] = m;
    __syncthreads();
    m = redm[0];
#pragma unroll
    for (int i = 1; i < 8; i++) m = fmaxf(m, redm[i]);

    v.x = __expf(v.x - m); v.y = __expf(v.y - m);
    v.z = __expf(v.z - m); v.w = __expf(v.w - m);
    float s = v.x + v.y + v.z + v.w;
#pragma unroll
    for (int o = 16; o; o >>= 1) s += __shfl_xor_sync(0xffffffffu, s, o);
    if (lane == 0) reds[wid] = s;
    __syncthreads();
    s = reds[0];
#pragma unroll
    for (int i = 1; i < 8; i++) s += reds[i];

    float inv = 1.0f / s;
    v.x *= inv; v.y *= inv; v.z *= inv; v.w *= inv;
    p[t] = v;

    size_t o = row * SEQ + (size_t)t * 4;
    bf16 h,l; bf162 th, tl;
    split1(v.x,h,l); th.x=h; tl.x=l; split1(v.y,h,l); th.y=h; tl.y=l;
    *(bf162*)(g_Ah+o) = th; *(bf162*)(g_Al+o) = tl;
    split1(v.z,h,l); th.x=h; tl.x=l; split1(v.w,h,l); th.y=h; tl.y=l;
    *(bf162*)(g_Ah+o+2) = th; *(bf162*)(g_Al+o+2) = tl;
}

// ---------------- CLS row ----------------
__global__ void cls_kernel(const float* __restrict__ x)
{
    int bh = blockIdx.x;
    int b = bh / NH, h = bh % NH;
    int d = threadIdx.x;  // 64 threads
    __shared__ float cks[SEQ];
    for (int k = d; k < SEQ; k += 64) cks[k] = g_ck[bh * SEQ + k];
    __syncthreads();
    const float* V = g_V + (size_t)b * SEQ * EMB + h * HD + d;
    float acc = 0.f;
#pragma unroll 8
    for (int k = 0; k < SEQ; k++) acc += cks[k] * V[(size_t)k * EMB];
    float cls = x[(size_t)b * SFULL * EMB + h * HD + d];
    float y = 0.5f * (cls + acc);
    size_t o = (size_t)b * SFULL * EMB + h * HD + d;
    bf16 hh, ll; split1(y, hh, ll);
    g_Yh[o] = hh; g_Yl[o] = ll;
}

// ---------------------------------------------------------------------------
extern "C" void kernel_launch(void* const* d_in, const int* in_sizes, int n_in,
                              void* d_out, int out_size)
{
    const float* x  = (const float*)d_in[0];
    const float* Wq = (const float*)d_in[1]; const float* bq = (const float*)d_in[2];
    const float* Wk = (const float*)d_in[3]; const float* bk = (const float*)d_in[4];
    const float* Wv = (const float*)d_in[5]; const float* bv = (const float*)d_in[6];
    const float* Wc = (const float*)d_in[7]; const float* bc = (const float*)d_in[8];
    const float* Wo = (const float*)d_in[9]; const float* bo = (const float*)d_in[10];

    float* out  = (float*)d_out;
    float* attn = out + (size_t)NB * SFULL * EMB;

    int nx4 = NB*SFULL*EMB/4, nw4 = EMB*EMB/4;
    convert_split<<<(nx4+255)/256, 256>>>(x, 0, nx4);
    convert_split<<<(nw4+255)/256, 256>>>(Wq, 1, nw4);
    convert_split<<<(nw4+255)/256, 256>>>(Wk, 2, nw4);
    convert_split<<<(nw4+255)/256, 256>>>(Wv, 3, nw4);
    convert_split<<<(nw4+255)/256, 256>>>(Wo, 4, nw4);

    qkv_tc<<<dim3(6, 64, 3), 256>>>(bq, bk, bv);
    cproj_kernel<<<8, 256>>>(x, Wc, bc);
    coef_kernel<<<dim3(12288, 2), 256>>>();
    score_tc<<<dim3(8, 8, 96), 256>>>(attn);
    softmax_kernel<<<BH * SEQ, 256>>>(attn);
    av_tc<<<dim3(8, 96), 256>>>();
    cls_kernel<<<96, 64>>>(x);
    out_tc<<<dim3(6, 65), 256>>>(bo, out);
}

// round 5
// speedup vs baseline: 1.4197x; 1.1488x over previous
#include <cuda_runtime.h>
#include <cuda_bf16.h>

#define NB 8
#define SEQ 1024
#define SFULL 1025
#define EMB 768
#define NH 12
#define HD 64
#define BH (NB*NH)   // 96
#define MOUT (NB*SFULL) // 8200

typedef unsigned u32;
typedef __nv_bfloat16 bf16;
typedef __nv_bfloat162 bf162;

// ---------------- static scratch ----------------
__device__ float g_Q[NB*SEQ*EMB];
__device__ float g_K[NB*SEQ*EMB];
__device__ float g_V[NB*SEQ*EMB];
__device__ float g_C[NB*EMB];
__device__ float g_coef[BH*SEQ];
__device__ float g_ck[BH*SEQ];

__device__ bf16 g_xh[NB*SFULL*EMB], g_xl[NB*SFULL*EMB];
__device__ bf16 g_Wqh[EMB*EMB], g_Wql[EMB*EMB];
__device__ bf16 g_Wkh[EMB*EMB], g_Wkl[EMB*EMB];
__device__ bf16 g_Wvh[EMB*EMB], g_Wvl[EMB*EMB];
__device__ bf16 g_Woh[EMB*EMB], g_Wol[EMB*EMB];
__device__ bf16 g_Qh[NB*SEQ*EMB], g_Ql[NB*SEQ*EMB];
__device__ bf16 g_Kh[NB*SEQ*EMB], g_Kl[NB*SEQ*EMB];
__device__ bf16 g_Vh[NB*SEQ*EMB], g_Vl[NB*SEQ*EMB];
__device__ bf16 g_Ah[(size_t)BH*SEQ*SEQ], g_Al[(size_t)BH*SEQ*SEQ];
__device__ bf16 g_Yh[NB*SFULL*EMB], g_Yl[NB*SFULL*EMB];

// ---------------- helpers ----------------
__device__ __forceinline__ void mma_bf16(float* d, const u32* a, const u32* b) {
    asm("mma.sync.aligned.m16n8k16.row.col.f32.bf16.bf16.f32 "
        "{%0,%1,%2,%3},{%4,%5,%6,%7},{%8,%9},{%0,%1,%2,%3};"
        : "+f"(d[0]), "+f"(d[1]), "+f"(d[2]), "+f"(d[3])
        : "r"(a[0]), "r"(a[1]), "r"(a[2]), "r"(a[3]), "r"(b[0]), "r"(b[1]));
}
__device__ __forceinline__ void ldsm4(u32& r0,u32& r1,u32& r2,u32& r3, u32 addr){
    asm volatile("ldmatrix.sync.aligned.m8n8.x4.shared.b16 {%0,%1,%2,%3},[%4];"
        : "=r"(r0),"=r"(r1),"=r"(r2),"=r"(r3) : "r"(addr));
}
__device__ __forceinline__ void ldsm4t(u32& r0,u32& r1,u32& r2,u32& r3, u32 addr){
    asm volatile("ldmatrix.sync.aligned.m8n8.x4.trans.shared.b16 {%0,%1,%2,%3},[%4];"
        : "=r"(r0),"=r"(r1),"=r"(r2),"=r"(r3) : "r"(addr));
}
__device__ __forceinline__ u32 sptr(const void* p){
    return (u32)__cvta_generic_to_shared(p);
}
// swizzled smem index (stride 24 bf16/row, XOR 8-col halves by row bit3)
__device__ __forceinline__ int sx(int r, int c) { return r*24 + (c ^ (((r>>3)&1)<<3)); }

__device__ __forceinline__ void split1(float v, bf16& h, bf16& l) {
    h = __float2bfloat16(v);
    l = __float2bfloat16(v - __bfloat162float(h));
}

// Load MT m16k16 A fragments (h and l) via ldmatrix.x4
template<int MT>
__device__ __forceinline__ void load_afrag(u32 Ah[][4], u32 Al[][4],
                                           u32 baseh, u32 basel, int rbase, int lane)
{
    int r = rbase + (lane & 15);
    int kc = (lane >> 4) << 3;
#pragma unroll
    for (int i = 0; i < MT; i++) {
        u32 off = 2u * sx(r + 16*i, kc);
        ldsm4(Ah[i][0],Ah[i][1],Ah[i][2],Ah[i][3], baseh + off);
        ldsm4(Al[i][0],Al[i][1],Al[i][2],Al[i][3], basel + off);
    }
}

// 3-term mma over MT x NT tile block; B from swizzled row-major [n][k] smem.
template<int MT, int NT>
__device__ __forceinline__ void mma_block(
    float acc[MT][NT][4], const u32 Ah[][4], const u32 Al[][4],
    u32 bbh, u32 bbl, int cbase, int lane)
{
    int nrow = (lane & 7) + ((lane >> 4) << 3);
    int kc = ((lane >> 3) & 1) << 3;
#pragma unroll
    for (int jp = 0; jp < NT/2; jp++) {
        u32 off = 2u * sx(cbase + 16*jp + nrow, kc);
        u32 bh[4], bl[4];
        ldsm4(bh[0],bh[1],bh[2],bh[3], bbh + off);
        ldsm4(bl[0],bl[1],bl[2],bl[3], bbl + off);
#pragma unroll
        for (int i = 0; i < MT; i++) {
            mma_bf16(acc[i][2*jp],   Ah[i], bh);
            mma_bf16(acc[i][2*jp],   Ah[i], bl);
            mma_bf16(acc[i][2*jp],   Al[i], bh);
            mma_bf16(acc[i][2*jp+1], Ah[i], bh+2);
            mma_bf16(acc[i][2*jp+1], Ah[i], bl+2);
            mma_bf16(acc[i][2*jp+1], Al[i], bh+2);
        }
    }
}

// ---------------- split conversion ----------------
__global__ __launch_bounds__(256) void convert_split(const float* __restrict__ src, int tag, int n4)
{
    int i = blockIdx.x * 256 + threadIdx.x;
    if (i >= n4) return;
    bf16 *h, *l;
    if (tag == 0)      { h = g_xh;  l = g_xl;  }
    else if (tag == 1) { h = g_Wqh; l = g_Wql; }
    else if (tag == 2) { h = g_Wkh; l = g_Wkl; }
    else if (tag == 3) { h = g_Wvh; l = g_Wvl; }
    else               { h = g_Woh; l = g_Wol; }
    float4 v = ((const float4*)src)[i];
    bf16 h0,l0,h1,l1,h2,l2,h3,l3;
    split1(v.x,h0,l0); split1(v.y,h1,l1); split1(v.z,h2,l2); split1(v.w,h3,l3);
    bf162 hh0; hh0.x=h0; hh0.y=h1;  bf162 hh1; hh1.x=h2; hh1.y=h3;
    bf162 ll0; ll0.x=l0; ll0.y=l1;  bf162 ll1; ll1.x=l2; ll1.y=l3;
    ((bf162*)h)[2*i] = hh0; ((bf162*)h)[2*i+1] = hh1;
    ((bf162*)l)[2*i] = ll0; ((bf162*)l)[2*i+1] = ll1;
}

// ---------------- QKV projection (tensor) ----------------
__global__ __launch_bounds__(256,1) void qkv_tc(
    const float* __restrict__ bq, const float* __restrict__ bk, const float* __restrict__ bv)
{
    const bf16 *Wh, *Wl; const float* bias; float* Cf; bf16 *Ch, *Cl;
    int z = blockIdx.z;
    if (z == 0)      { Wh=g_Wqh; Wl=g_Wql; bias=bq; Cf=g_Q; Ch=g_Qh; Cl=g_Ql; }
    else if (z == 1) { Wh=g_Wkh; Wl=g_Wkl; bias=bk; Cf=g_K; Ch=g_Kh; Cl=g_Kl; }
    else             { Wh=g_Wvh; Wl=g_Wvl; bias=bv; Cf=g_V; Ch=g_Vh; Cl=g_Vl; }

    __shared__ bf16 SAh[128*24], SAl[128*24], SBh[128*24], SBl[128*24];
    u32 pAh = sptr(SAh), pAl = sptr(SAl), pBh = sptr(SBh), pBl = sptr(SBl);
    int tid = threadIdx.x;
    int lane = tid & 31, wid = tid >> 5;
    int gid = lane >> 2, tig = lane & 3;
    int wm = wid >> 1, wn = wid & 1;
    int bm = blockIdx.y, bn = blockIdx.x;

    int arow = tid >> 1, ahalf = (tid & 1) << 3;
    int grow = bm*128 + arow;
    size_t aoff = (size_t)((grow>>10)*SFULL + 1 + (grow&1023)) * EMB + ahalf;
    size_t boff = (size_t)(bn*128 + arow) * EMB + ahalf;

    float acc[2][8][4];
#pragma unroll
    for (int i=0;i<2;i++)
#pragma unroll
        for (int j=0;j<8;j++)
#pragma unroll
            for (int q=0;q<4;q++) acc[i][j][q]=0.f;

    uint4 rAh = *(const uint4*)(g_xh + aoff);
    uint4 rAl = *(const uint4*)(g_xl + aoff);
    uint4 rBh = *(const uint4*)(Wh + boff);
    uint4 rBl = *(const uint4*)(Wl + boff);

    const int NK = EMB/16;
    for (int ks = 0; ks < NK; ks++) {
        if (ks) __syncthreads();
        *(uint4*)&SAh[sx(arow, ahalf)] = rAh;
        *(uint4*)&SAl[sx(arow, ahalf)] = rAl;
        *(uint4*)&SBh[sx(arow, ahalf)] = rBh;
        *(uint4*)&SBl[sx(arow, ahalf)] = rBl;
        __syncthreads();
        if (ks+1 < NK) {
            size_t k2 = (size_t)(ks+1)*16;
            rAh = *(const uint4*)(g_xh + aoff + k2);
            rAl = *(const uint4*)(g_xl + aoff + k2);
            rBh = *(const uint4*)(Wh + boff + k2);
            rBl = *(const uint4*)(Wl + boff + k2);
        }
        u32 Ahf[2][4], Alf[2][4];
        load_afrag<2>(Ahf, Alf, pAh, pAl, wm*32, lane);
        mma_block<2,8>(acc, Ahf, Alf, pBh, pBl, wn*64, lane);
    }

#pragma unroll
    for (int i=0;i<2;i++) {
        int row0 = bm*128 + wm*32 + 16*i + gid;
#pragma unroll
        for (int j=0;j<8;j++) {
            int col0 = bn*128 + wn*64 + 8*j + 2*tig;
            float2 bv2 = *(const float2*)(bias + col0);
            float v0 = acc[i][j][0]+bv2.x, v1 = acc[i][j][1]+bv2.y;
            float v2 = acc[i][j][2]+bv2.x, v3 = acc[i][j][3]+bv2.y;
            size_t o0 = (size_t)row0*EMB + col0, o8 = (size_t)(row0+8)*EMB + col0;
            *(float2*)(Cf+o0) = make_float2(v0,v1);
            *(float2*)(Cf+o8) = make_float2(v2,v3);
            bf16 h,l; bf162 th, tl;
            split1(v0,h,l); th.x=h; tl.x=l; split1(v1,h,l); th.y=h; tl.y=l;
            *(bf162*)(Ch+o0)=th; *(bf162*)(Cl+o0)=tl;
            split1(v2,h,l); th.x=h; tl.x=l; split1(v3,h,l); th.y=h; tl.y=l;
            *(bf162*)(Ch+o8)=th; *(bf162*)(Cl+o8)=tl;
        }
    }
}

// ---------------- out projection (tensor) ----------------
__global__ __launch_bounds__(256,1) void out_tc(const float* __restrict__ bo, float* __restrict__ out)
{
    __shared__ bf16 SAh[128*24], SAl[128*24], SBh[128*24], SBl[128*24];
    u32 pAh = sptr(SAh), pAl = sptr(SAl), pBh = sptr(SBh), pBl = sptr(SBl);
    int tid = threadIdx.x;
    int lane = tid & 31, wid = tid >> 5;
    int gid = lane >> 2, tig = lane & 3;
    int wm = wid >> 1, wn = wid & 1;
    int bm = blockIdx.y, bn = blockIdx.x;

    int arow = tid >> 1, ahalf = (tid & 1) << 3;
    int grow = bm*128 + arow; if (grow >= MOUT) grow = MOUT-1;
    size_t aoff = (size_t)grow * EMB + ahalf;
    size_t boff = (size_t)(bn*128 + arow) * EMB + ahalf;

    float acc[2][8][4];
#pragma unroll
    for (int i=0;i<2;i++)
#pragma unroll
        for (int j=0;j<8;j++)
#pragma unroll
            for (int q=0;q<4;q++) acc[i][j][q]=0.f;

    uint4 rAh = *(const uint4*)(g_Yh + aoff);
    uint4 rAl = *(const uint4*)(g_Yl + aoff);
    uint4 rBh = *(const uint4*)(g_Woh + boff);
    uint4 rBl = *(const uint4*)(g_Wol + boff);

    const int NK = EMB/16;
    for (int ks = 0; ks < NK; ks++) {
        if (ks) __syncthreads();
        *(uint4*)&SAh[sx(arow, ahalf)] = rAh;
        *(uint4*)&SAl[sx(arow, ahalf)] = rAl;
        *(uint4*)&SBh[sx(arow, ahalf)] = rBh;
        *(uint4*)&SBl[sx(arow, ahalf)] = rBl;
        __syncthreads();
        if (ks+1 < NK) {
            size_t k2 = (size_t)(ks+1)*16;
            rAh = *(const uint4*)(g_Yh + aoff + k2);
            rAl = *(const uint4*)(g_Yl + aoff + k2);
            rBh = *(const uint4*)(g_Woh + boff + k2);
            rBl = *(const uint4*)(g_Wol + boff + k2);
        }
        u32 Ahf[2][4], Alf[2][4];
        load_afrag<2>(Ahf, Alf, pAh, pAl, wm*32, lane);
        mma_block<2,8>(acc, Ahf, Alf, pBh, pBl, wn*64, lane);
    }

#pragma unroll
    for (int i=0;i<2;i++) {
        int row0 = bm*128 + wm*32 + 16*i + gid;
#pragma unroll
        for (int j=0;j<8;j++) {
            int col0 = bn*128 + wn*64 + 8*j + 2*tig;
            float2 bv2 = *(const float2*)(bo + col0);
            if (row0 < MOUT)
                *(float2*)(out + (size_t)row0*EMB + col0) =
                    make_float2(acc[i][j][0]+bv2.x, acc[i][j][1]+bv2.y);
            if (row0+8 < MOUT)
                *(float2*)(out + (size_t)(row0+8)*EMB + col0) =
                    make_float2(acc[i][j][2]+bv2.x, acc[i][j][3]+bv2.y);
        }
    }
}

// ---------------- score (tensor) ----------------
__global__ __launch_bounds__(256,1) void score_tc(float* __restrict__ attn)
{
    int bh = blockIdx.z;
    int b = bh / NH, h = bh % NH;
    __shared__ bf16 SAh[128*24], SAl[128*24], SBh[128*24], SBl[128*24];
    u32 pAh = sptr(SAh), pAl = sptr(SAl), pBh = sptr(SBh), pBl = sptr(SBl);
    int tid = threadIdx.x;
    int lane = tid & 31, wid = tid >> 5;
    int gid = lane >> 2, tig = lane & 3;
    int wm = wid >> 1, wn = wid & 1;
    int bm = blockIdx.y, bn = blockIdx.x;

    int arow = tid >> 1, ahalf = (tid & 1) << 3;
    size_t aoff = (size_t)(b*SEQ + bm*128 + arow)*EMB + h*HD + ahalf;
    size_t boff = (size_t)(b*SEQ + bn*128 + arow)*EMB + h*HD + ahalf;

    float acc[2][8][4];
#pragma unroll
    for (int i=0;i<2;i++)
#pragma unroll
        for (int j=0;j<8;j++)
#pragma unroll
            for (int q=0;q<4;q++) acc[i][j][q]=0.f;

    uint4 rAh = *(const uint4*)(g_Qh + aoff);
    uint4 rAl = *(const uint4*)(g_Ql + aoff);
    uint4 rBh = *(const uint4*)(g_Kh + boff);
    uint4 rBl = *(const uint4*)(g_Kl + boff);

    const int NK = HD/16;
    for (int ks = 0; ks < NK; ks++) {
        if (ks) __syncthreads();
        *(uint4*)&SAh[sx(arow, ahalf)] = rAh;
        *(uint4*)&SAl[sx(arow, ahalf)] = rAl;
        *(uint4*)&SBh[sx(arow, ahalf)] = rBh;
        *(uint4*)&SBl[sx(arow, ahalf)] = rBl;
        __syncthreads();
        if (ks+1 < NK) {
            size_t k2 = (size_t)(ks+1)*16;
            rAh = *(const uint4*)(g_Qh + aoff + k2);
            rAl = *(const uint4*)(g_Ql + aoff + k2);
            rBh = *(const uint4*)(g_Kh + boff + k2);
            rBl = *(const uint4*)(g_Kl + boff + k2);
        }
        u32 Ahf[2][4], Alf[2][4];
        load_afrag<2>(Ahf, Alf, pAh, pAl, wm*32, lane);
        mma_block<2,8>(acc, Ahf, Alf, pBh, pBl, wn*64, lane);
    }

    float* Cb = attn + (size_t)bh*SEQ*SEQ;
    const float* coefp = g_coef + bh*SEQ;
#pragma unroll
    for (int i=0;i<2;i++) {
        int row0 = bm*128 + wm*32 + 16*i + gid;
        float cf0 = coefp[row0], cf8 = coefp[row0+8];
#pragma unroll
        for (int j=0;j<8;j++) {
            int col0 = bn*128 + wn*64 + 8*j + 2*tig;
            *(float2*)(Cb + (size_t)row0*SEQ + col0) =
                make_float2(acc[i][j][0]*cf0, acc[i][j][1]*cf0);
            *(float2*)(Cb + (size_t)(row0+8)*SEQ + col0) =
                make_float2(acc[i][j][2]*cf8, acc[i][j][3]*cf8);
        }
    }
}

// ---------------- attn @ V (tensor) ----------------
// per bh: M=1024, N=64, K=1024 (64 steps). V staged [k][d] natural, ldmatrix.trans.
__global__ __launch_bounds__(256,1) void av_tc()
{
    int bh = blockIdx.y;
    int b = bh / NH, h = bh % NH;
    __shared__ bf16 SAh[128*24], SAl[128*24], SVh[16*72], SVl[16*72];
    u32 pAh = sptr(SAh), pAl = sptr(SAl), pVh = sptr(SVh), pVl = sptr(SVl);
    int tid = threadIdx.x;
    int lane = tid & 31, wid = tid >> 5;
    int gid = lane >> 2, tig = lane & 3;
    int wm = wid >> 1, wn = wid & 1;
    int bm = blockIdx.x;

    int arow = tid >> 1, ahalf = (tid & 1) << 3;
    size_t aoff = (size_t)(bh*SEQ + bm*128 + arow)*SEQ + ahalf;

    int tv = tid & 127;
    int vk = tv >> 3, vd0 = (tv & 7) << 3;
    const bf16* Vsrc = (tid < 128) ? g_Vh : g_Vl;
    bf16* SV = (tid < 128) ? SVh : SVl;
    size_t voff = (size_t)(b*SEQ + vk)*EMB + h*HD + vd0;

    float acc[2][4][4];
#pragma unroll
    for (int i=0;i<2;i++)
#pragma unroll
        for (int j=0;j<4;j++)
#pragma unroll
            for (int q=0;q<4;q++) acc[i][j][q]=0.f;

    uint4 rAh = *(const uint4*)(g_Ah + aoff);
    uint4 rAl = *(const uint4*)(g_Al + aoff);
    uint4 rV  = *(const uint4*)(Vsrc + voff);

    // B-frag (trans) lane addressing within 16x16 region of SV[k][72]
    int bk = (lane & 7) + (((lane >> 3) & 1) << 3);
    int bdoff = (lane >> 4) << 3;

    const int NK = SEQ/16;
    for (int ks = 0; ks < NK; ks++) {
        if (ks) __syncthreads();
        *(uint4*)&SAh[sx(arow, ahalf)] = rAh;
        *(uint4*)&SAl[sx(arow, ahalf)] = rAl;
        *(uint4*)&SV[vk*72 + vd0] = rV;
        __syncthreads();
        if (ks+1 < NK) {
            rAh = *(const uint4*)(g_Ah + aoff + (ks+1)*16);
            rAl = *(const uint4*)(g_Al + aoff + (ks+1)*16);
            rV  = *(const uint4*)(Vsrc + voff + (size_t)(ks+1)*16*EMB);
        }
        u32 Ahf[2][4], Alf[2][4];
        load_afrag<2>(Ahf, Alf, pAh, pAl, wm*32, lane);
#pragma unroll
        for (int jp = 0; jp < 2; jp++) {
            int d = wn*32 + 16*jp + bdoff;
            u32 off = 2u * (bk*72 + d);
            u32 bhf[4], blf[4];
            ldsm4t(bhf[0],bhf[1],bhf[2],bhf[3], pVh + off);
            ldsm4t(blf[0],blf[1],blf[2],blf[3], pVl + off);
#pragma unroll
            for (int i = 0; i < 2; i++) {
                mma_bf16(acc[i][2*jp],   Ahf[i], bhf);
                mma_bf16(acc[i][2*jp],   Ahf[i], blf);
                mma_bf16(acc[i][2*jp],   Alf[i], bhf);
                mma_bf16(acc[i][2*jp+1], Ahf[i], bhf+2);
                mma_bf16(acc[i][2*jp+1], Ahf[i], blf+2);
                mma_bf16(acc[i][2*jp+1], Alf[i], bhf+2);
            }
        }
    }

#pragma unroll
    for (int i=0;i<2;i++) {
        int row0 = bm*128 + wm*32 + 16*i + gid;
#pragma unroll
        for (int j=0;j<4;j++) {
            int col0 = wn*32 + 8*j + 2*tig;
            size_t o0 = (size_t)(b*SFULL + 1 + row0)*EMB + h*HD + col0;
            size_t o8 = (size_t)(b*SFULL + 9 + row0)*EMB + h*HD + col0;
            bf16 hh,ll; bf162 th, tl;
            split1(acc[i][j][0],hh,ll); th.x=hh; tl.x=ll;
            split1(acc[i][j][1],hh,ll); th.y=hh; tl.y=ll;
            *(bf162*)(g_Yh+o0)=th; *(bf162*)(g_Yl+o0)=tl;
            split1(acc[i][j][2],hh,ll); th.x=hh; tl.x=ll;
            split1(acc[i][j][3],hh,ll); th.y=hh; tl.y=ll;
            *(bf162*)(g_Yh+o8)=th; *(bf162*)(g_Yl+o8)=tl;
        }
    }
}

// ---------------- c projection ----------------
__global__ void cproj_kernel(const float* __restrict__ x,
                             const float* __restrict__ Wc,
                             const float* __restrict__ bc)
{
    int b = blockIdx.x;
    __shared__ float xs[EMB];
    for (int e = threadIdx.x; e < EMB; e += blockDim.x)
        xs[e] = x[(size_t)b * SFULL * EMB + e];
    __syncthreads();
    for (int j = threadIdx.x; j < EMB; j += blockDim.x) {
        const float* w = Wc + (size_t)j * EMB;
        float acc = bc[j];
        for (int e = 0; e < EMB; e++) acc += xs[e] * w[e];
        g_C[b * EMB + j] = acc;
    }
}

// ---------------- coefficients ----------------
__global__ __launch_bounds__(256) void coef_kernel()
{
    int gw = blockIdx.x * 8 + (threadIdx.x >> 5);
    int lane = threadIdx.x & 31;
    int q = gw & (SEQ - 1);
    int bh = gw >> 10;
    int b = bh / NH, h = bh % NH;
    const float* src = (blockIdx.y == 0) ? g_Q : g_K;
    const float* qp = src + (size_t)(b * SEQ + q) * EMB + h * HD;
    const float* cp = g_C + b * EMB + h * HD;
    float q0 = qp[lane], q1 = qp[lane + 32];
    float c0 = cp[lane], c1 = cp[lane + 32];
    float qn = q0*q0 + q1*q1;
    float cq = c0*q0 + c1*q1;
    float cn = c0*c0 + c1*c1;
#pragma unroll
    for (int o = 16; o; o >>= 1) {
        qn += __shfl_xor_sync(0xffffffffu, qn, o);
        cq += __shfl_xor_sync(0xffffffffu, cq, o);
        cn += __shfl_xor_sync(0xffffffffu, cn, o);
    }
    if (lane == 0) {
        float cn2 = fmaxf(cn, 1e-5f);
        if (blockIdx.y == 0) {
            float qn2 = fmaxf(qn, 1e-5f);
            g_coef[gw] = cq / (qn2 * sqrtf(64.0f * cn2));
        } else {
            g_ck[gw] = cq / sqrtf(64.0f * cn2);
        }
    }
}

// ---------------- softmax (fp32 in-place + bf16 split out) ----------------
__global__ __launch_bounds__(256) void softmax_kernel(float* __restrict__ attn)
{
    size_t row = blockIdx.x;
    float4* p = (float4*)(attn + row * SEQ);
    int t = threadIdx.x;
    int wid = t >> 5, lane = t & 31;
    __shared__ float redm[8], reds[8];

    float4 v = p[t];
    float m = fmaxf(fmaxf(v.x, v.y), fmaxf(v.z, v.w));
#pragma unroll
    for (int o = 16; o; o >>= 1) m = fmaxf(m, __shfl_xor_sync(0xffffffffu, m, o));
    if (lane == 0) redm[wid] = m;
    __syncthreads();
    m = redm[0];
#pragma unroll
    for (int i = 1; i < 8; i++) m = fmaxf(m, redm[i]);

    v.x = __expf(v.x - m); v.y = __expf(v.y - m);
    v.z = __expf(v.z - m); v.w = __expf(v.w - m);
    float s = v.x + v.y + v.z + v.w;
#pragma unroll
    for (int o = 16; o; o >>= 1) s += __shfl_xor_sync(0xffffffffu, s, o);
    if (lane == 0) reds[wid] = s;
    __syncthreads();
    s = reds[0];
#pragma unroll
    for (int i = 1; i < 8; i++) s += reds[i];

    float inv = 1.0f / s;
    v.x *= inv; v.y *= inv; v.z *= inv; v.w *= inv;
    p[t] = v;

    size_t o = row * SEQ + (size_t)t * 4;
    bf16 h,l; bf162 th, tl;
    split1(v.x,h,l); th.x=h; tl.x=l; split1(v.y,h,l); th.y=h; tl.y=l;
    *(bf162*)(g_Ah+o) = th; *(bf162*)(g_Al+o) = tl;
    split1(v.z,h,l); th.x=h; tl.x=l; split1(v.w,h,l); th.y=h; tl.y=l;
    *(bf162*)(g_Ah+o+2) = th; *(bf162*)(g_Al+o+2) = tl;
}

// ---------------- CLS row ----------------
__global__ void cls_kernel(const float* __restrict__ x)
{
    int bh = blockIdx.x;
    int b = bh / NH, h = bh % NH;
    int d = threadIdx.x;  // 64 threads
    __shared__ float cks[SEQ];
    for (int k = d; k < SEQ; k += 64) cks[k] = g_ck[bh * SEQ + k];
    __syncthreads();
    const float* V = g_V + (size_t)b * SEQ * EMB + h * HD + d;
    float acc = 0.f;
#pragma unroll 8
    for (int k = 0; k < SEQ; k++) acc += cks[k] * V[(size_t)k * EMB];
    float cls = x[(size_t)b * SFULL * EMB + h * HD + d];
    float y = 0.5f * (cls + acc);
    size_t o = (size_t)b * SFULL * EMB + h * HD + d;
    bf16 hh, ll; split1(y, hh, ll);
    g_Yh[o] = hh; g_Yl[o] = ll;
}

// ---------------------------------------------------------------------------
extern "C" void kernel_launch(void* const* d_in, const int* in_sizes, int n_in,
                              void* d_out, int out_size)
{
    const float* x  = (const float*)d_in[0];
    const float* Wq = (const float*)d_in[1]; const float* bq = (const float*)d_in[2];
    const float* Wk = (const float*)d_in[3]; const float* bk = (const float*)d_in[4];
    const float* Wv = (const float*)d_in[5]; const float* bv = (const float*)d_in[6];
    const float* Wc = (const float*)d_in[7]; const float* bc = (const float*)d_in[8];
    const float* Wo = (const float*)d_in[9]; const float* bo = (const float*)d_in[10];

    float* out  = (float*)d_out;
    float* attn = out + (size_t)NB * SFULL * EMB;

    int nx4 = NB*SFULL*EMB/4, nw4 = EMB*EMB/4;
    convert_split<<<(nx4+255)/256, 256>>>(x, 0, nx4);
    convert_split<<<(nw4+255)/256, 256>>>(Wq, 1, nw4);
    convert_split<<<(nw4+255)/256, 256>>>(Wk, 2, nw4);
    convert_split<<<(nw4+255)/256, 256>>>(Wv, 3, nw4);
    convert_split<<<(nw4+255)/256, 256>>>(Wo, 4, nw4);

    qkv_tc<<<dim3(6, 64, 3), 256>>>(bq, bk, bv);
    cproj_kernel<<<8, 256>>>(x, Wc, bc);
    coef_kernel<<<dim3(12288, 2), 256>>>();
    score_tc<<<dim3(8, 8, 96), 256>>>(attn);
    softmax_kernel<<<BH * SEQ, 256>>>(attn);
    av_tc<<<dim3(8, 96), 256>>>();
    cls_kernel<<<96, 64>>>(x);
    out_tc<<<dim3(6, 65), 256>>>(bo, out);
}